// round 11
// baseline (speedup 1.0000x reference)
#include <cuda_runtime.h>
#include <cuda_bf16.h>
#include <mma.h>
#include <cstdint>
#include <cstddef>

using namespace nvcuda;

#define BATCH 64
#define TLEN  512
#define EMBD  512
#define HID   1024
#define G4    4096
#define NTAG  10
#define ROWS  (BATCH*TLEN)          // 32768
#define RBLK  128                   // persistent blocks in recurrent kernel

// ---------------- cp.async helpers ----------------
__device__ __forceinline__ void cp16(void* dst, const void* src) {
    unsigned d = (unsigned)__cvta_generic_to_shared(dst);
    asm volatile("cp.async.cg.shared.global [%0], [%1], 16;\n" :: "r"(d), "l"(src));
}
__device__ __forceinline__ void cp_commit() { asm volatile("cp.async.commit_group;\n"); }
template<int N> __device__ __forceinline__ void cp_wait() {
    asm volatile("cp.async.wait_group %0;\n" :: "n"(N));
}
__device__ __forceinline__ float tanh_fast(float x) {
    float y; asm("tanh.approx.f32 %0, %1;" : "=f"(y) : "f"(x)); return y;
}

// ---------------- recur smem layout ----------------
#define RW_PITCH 1036                          // W slice pitch (floats)
#define R_AP 20                                // h-panel pitch (floats, 16 cols + pad)
#define R_AS_FLOATS (2*8*64*R_AP)              // 20480: double-buffered 8 K-regions
#define R_SMEM_FLOATS (32*RW_PITCH + R_AS_FLOATS)
#define R_SMEM_BYTES  (R_SMEM_FLOATS * 4)      // 214,528 B

// ---------------- xproj smem layout ----------------
#define X_AP 36
#define X_SMEM_FLOATS (2*128*X_AP*2)           // As[2][128][36] + Bs[2][128][36]
#define X_SMEM_BYTES  (X_SMEM_FLOATS * 4)      // 73,728 B

// ---------------- device scratch (static: no allocations allowed) ----------------
__device__ float g_seq0[(size_t)ROWS*EMBD];     // embeddings, t-major rows (t*64+b)
__device__ float g_xp  [(size_t)ROWS*G4];       // x_proj scratch (reused by both layers)
__device__ float g_hseq[(size_t)ROWS*HID];      // layer-0 hidden sequence
__device__ float g_h[2][BATCH*HID];             // double-buffered recurrent h
__device__ float g_lasth[BATCH*HID];            // layer-1 h at t = lens-1
__device__ float g_Wih0p[(size_t)G4*EMBD];      // gate-permuted, tf32-rounded weights
__device__ float g_Whh0p[(size_t)G4*HID];
__device__ float g_Wih1p[(size_t)G4*HID];
__device__ float g_Whh1p[(size_t)G4*HID];
__device__ float g_b0p[G4];
__device__ float g_b1p[G4];
__device__ int   g_tt[BATCH];                   // target timestep per batch (lens-1)
__device__ unsigned g_barcnt = 0;               // monotonic grid-barrier ticket counter

// ---------------- grid barrier: monotonic ticket, release/acquire ----------------
// g_barcnt is always a multiple of RBLK between kernels, so the tickets of
// barrier k within a launch occupy [base+128k, base+128k+127] and
// target = (ticket/128 + 1)*128 needs no per-launch bookkeeping.
// bar.sync cumulativity + atom.release / ld.acquire gives the hb chain
// (block writes -> release-add -> acquire-load -> reader) without MEMBAR.GPU.
__device__ __forceinline__ void grid_barrier() {
    __syncthreads();
    if (threadIdx.x == 0) {
        unsigned t;
        asm volatile("atom.add.release.gpu.global.u32 %0, [%1], 1;"
                     : "=r"(t) : "l"(&g_barcnt) : "memory");
        unsigned target = ((t >> 7) + 1u) << 7;
        unsigned cur;
        do {
            asm volatile("ld.acquire.gpu.global.u32 %0, [%1];"
                         : "=r"(cur) : "l"(&g_barcnt) : "memory");
        } while ((int)(cur - target) < 0);
    }
    __syncthreads();
}

// ---------------- preprocessing ----------------
// Permute gate rows: out row 4*j+g  <-  in row g*HID+j, round weights to tf32.
__global__ void permute_kernel(const float* __restrict__ Wih0, const float* __restrict__ Whh0,
                               const float* __restrict__ b0,
                               const float* __restrict__ Wih1, const float* __restrict__ Whh1,
                               const float* __restrict__ b1) {
    int p = blockIdx.x;                 // 0..4095
    int j = p >> 2, q = p & 3;
    size_t src = (size_t)(q * HID + j);
    for (int d = threadIdx.x; d < EMBD; d += blockDim.x)
        g_Wih0p[(size_t)p*EMBD + d] = wmma::__float_to_tf32(Wih0[src*EMBD + d]);
    for (int d = threadIdx.x; d < HID; d += blockDim.x) {
        g_Whh0p[(size_t)p*HID + d] = wmma::__float_to_tf32(Whh0[src*HID + d]);
        g_Wih1p[(size_t)p*HID + d] = wmma::__float_to_tf32(Wih1[src*HID + d]);
        g_Whh1p[(size_t)p*HID + d] = wmma::__float_to_tf32(Whh1[src*HID + d]);
    }
    if (threadIdx.x == 0) { g_b0p[p] = b0[src]; g_b1p[p] = b1[src]; }
}

// Embedding gather into t-major layout: row r = t*64 + b
__global__ void embed_kernel(const int* __restrict__ x, const float* __restrict__ emb) {
    int r = blockIdx.x;
    int b = r & 63, t = r >> 6;
    int tok = x[b * TLEN + t];
    const float4* src = (const float4*)&emb[(size_t)tok * EMBD];
    float4* dst = (float4*)&g_seq0[(size_t)r * EMBD];
    dst[threadIdx.x] = src[threadIdx.x];       // block = 128 threads = 128 float4
}

// lens + target timestep
__global__ void lens_kernel(const int* __restrict__ x) {
    __shared__ int red[8];
    int b = blockIdx.x;
    int c = 0;
    for (int t = threadIdx.x; t < TLEN; t += 256) c += (x[b * TLEN + t] == 0);
    #pragma unroll
    for (int o = 16; o > 0; o >>= 1) c += __shfl_down_sync(0xffffffffu, c, o);
    if ((threadIdx.x & 31) == 0) red[threadIdx.x >> 5] = c;
    __syncthreads();
    if (threadIdx.x == 0) {
        int tot = 0;
        #pragma unroll
        for (int w = 0; w < 8; w++) tot += red[w];
        int tt = TLEN - tot - 1;          // lens-1
        if (tt < 0) tt += TLEN;           // wrap like Python negative index
        g_tt[b] = tt;
    }
}

// ---------------- x_proj GEMM (pipelined): out[r][p] = sum_k A[r][k]*W[p][k] ----
// Block tile 128x128, 8 warps of 32x64, BK=32, 2-stage cp.async pipeline.
__global__ void __launch_bounds__(256, 2) xproj_kernel(const float* __restrict__ A,
                                                       const float* __restrict__ W,
                                                       float* __restrict__ out, int K) {
    extern __shared__ float xsm[];
    float* As = xsm;                        // [2][128][36]
    float* Bs = xsm + 2 * 128 * X_AP;       // [2][128][36]
    const int tid = threadIdx.x;
    const int warp = tid >> 5;
    const int m0 = blockIdx.y * 128, n0 = blockIdx.x * 128;
    const int wm = (warp & 3) * 32, wn = (warp >> 2) * 64;

    wmma::fragment<wmma::accumulator, 16, 16, 8, float> acc[2][4];
    #pragma unroll
    for (int i = 0; i < 2; i++)
        #pragma unroll
        for (int j = 0; j < 4; j++) wmma::fill_fragment(acc[i][j], 0.0f);

    const int sr = tid >> 3;                // 0..31
    const int sc = (tid & 7) << 2;          // 0..28

    auto stage = [&](int buf, int k0) {
        #pragma unroll
        for (int p = 0; p < 4; p++) {
            int r = sr + p * 32;
            cp16(&As[(buf * 128 + r) * X_AP + sc], &A[(size_t)(m0 + r) * K + k0 + sc]);
        }
        #pragma unroll
        for (int p = 0; p < 4; p++) {
            int r = sr + p * 32;
            cp16(&Bs[(buf * 128 + r) * X_AP + sc], &W[(size_t)(n0 + r) * K + k0 + sc]);
        }
        cp_commit();
    };

    stage(0, 0);
    stage(1, 32);
    const int NC = K >> 5;
    for (int ch = 0; ch < NC; ch++) {
        if (ch < NC - 1) cp_wait<1>(); else cp_wait<0>();
        __syncthreads();
        int buf = ch & 1;
        #pragma unroll
        for (int kk = 0; kk < 4; kk++) {
            wmma::fragment<wmma::matrix_a, 16, 16, 8, wmma::precision::tf32, wmma::row_major> af[2];
            wmma::fragment<wmma::matrix_b, 16, 16, 8, wmma::precision::tf32, wmma::col_major> bf[4];
            #pragma unroll
            for (int i = 0; i < 2; i++)
                wmma::load_matrix_sync(af[i], &As[(buf * 128 + wm + 16 * i) * X_AP + kk * 8], X_AP);
            #pragma unroll
            for (int j = 0; j < 4; j++)
                wmma::load_matrix_sync(bf[j], &Bs[(buf * 128 + wn + 16 * j) * X_AP + kk * 8], X_AP);
            #pragma unroll
            for (int i = 0; i < 2; i++)
                #pragma unroll
                for (int j = 0; j < 4; j++)
                    wmma::mma_sync(acc[i][j], af[i], bf[j], acc[i][j]);
        }
        __syncthreads();
        if (ch + 2 < NC) stage(buf, (ch + 2) * 32);
    }
    #pragma unroll
    for (int i = 0; i < 2; i++)
        #pragma unroll
        for (int j = 0; j < 4; j++)
            wmma::store_matrix_sync(&out[(size_t)(m0 + wm + 16 * i) * G4 + n0 + wn + 16 * j],
                                    acc[i][j], G4, wmma::mem_row_major);
}

// ---------------- persistent recurrent kernel ----------------
// 128 blocks x 512 threads; block bk owns permuted gate rows [32*bk, 32*bk+32)
// = hidden units [8*bk, 8*bk+8). 16 warps = 8 K-splits (128 cols) x 2 M-halves,
// warp tile 32x32. Warp-private staging (rows [mh,mh+32) x 16 cols/superstep)
// keeps the inner loop barrier-free: per-warp cp.async.wait + __syncwarp only.
// 4 warps/SMSP hide LDS->HMMA and L2 staging latency. Two block syncs per step
// (partials WAR + reduce), one grid barrier per step.
__global__ void __launch_bounds__(512) recur_kernel(const float* __restrict__ Whh,
                                                    const float* __restrict__ bias,
                                                    const float* __restrict__ xp,
                                                    int mode) {
    extern __shared__ float sm[];
    float* Ws = sm;                                 // [32][1036]
    float* As = Ws + 32 * RW_PITCH;                 // [2][8][64][20]
    float* Ps = As;                                 // partials [8ks][2nn][64][20] alias

    const int tid = threadIdx.x;
    const int warp = tid >> 5;
    const int lane = tid & 31;
    const int bk = blockIdx.x;
    const int ks = warp >> 1;                       // K-split 0..7 (128 cols each)
    const int mh = (warp & 1) * 32;                 // M half (batch rows)

    // ---- stage W slice rows [32*bk, 32*bk+32), full K=1024 (pre-tf32) ----
    for (int i = tid; i < 32 * 256; i += 512) {     // 256 float4 per gate row
        int r = i >> 8, c4 = (i & 255) << 2;
        float4 v = *(const float4*)&Whh[((size_t)(32 * bk + r)) * HID + c4];
        *(float4*)&Ws[r * RW_PITCH + c4] = v;
    }
    // per-thread persistent state: one (b, jj) pair per thread
    const int pb = tid >> 3, pj = tid & 7;          // b 0..63, jj 0..7
    const float4 bv = *(const float4*)&bias[32 * bk + pj * 4];
    const int ttb = g_tt[pb];
    float cst = 0.0f;                               // cell state
    g_h[0][pb * HID + 8 * bk + pj] = 0.0f;          // zero this block's h0 slice
    grid_barrier();                                 // W staged + h0 zeroed everywhere

    // warp-private staging geometry: 32 rows x 16 cols per superstep
    const int srow = lane >> 2;                     // 0..7  (+8 per i)
    const int scol = (lane & 3) << 2;               // 0,4,8,12

    const int pnn = pj >> 2;                        // which 16-col partial tile
    const int pcc = (pj & 3) << 2;                  // col within tile

    for (int t = 0; t < TLEN; t++) {
        const float* hprev = g_h[t & 1];
        float* hnext = g_h[(t + 1) & 1];

        // prefetch xp (independent of the recurrence)
        float4 xv = __ldg((const float4*)&xp[((size_t)(t * 64 + pb)) * G4 + 32 * bk + pj * 4]);

        wmma::fragment<wmma::accumulator, 16, 16, 8, float> acc[2][2];
        #pragma unroll
        for (int i = 0; i < 2; i++)
            #pragma unroll
            for (int j = 0; j < 2; j++) wmma::fill_fragment(acc[i][j], 0.0f);

        // warp-private stage: rows [mh, mh+32) x cols [ks*128+ss*16, +16)
        auto stage = [&](int buf, int ss) {
            #pragma unroll
            for (int i = 0; i < 4; i++) {
                int row = mh + i * 8 + srow;
                cp16(&As[((buf * 8 + ks) * 64 + row) * R_AP + scol],
                     &hprev[(size_t)row * HID + ks * 128 + ss * 16 + scol]);
            }
            cp_commit();
        };

        stage(0, 0);
        stage(1, 1);
        #pragma unroll
        for (int ss = 0; ss < 8; ss++) {
            if (ss < 7) cp_wait<1>(); else cp_wait<0>();
            __syncwarp();                           // staged data visible warp-wide
            int buf = ss & 1;
            #pragma unroll
            for (int kk = 0; kk < 2; kk++) {
                wmma::fragment<wmma::matrix_a, 16, 16, 8, wmma::precision::tf32, wmma::row_major> af[2];
                wmma::fragment<wmma::matrix_b, 16, 16, 8, wmma::precision::tf32, wmma::col_major> bf[2];
                #pragma unroll
                for (int mm = 0; mm < 2; mm++)
                    wmma::load_matrix_sync(af[mm],
                        &As[((buf * 8 + ks) * 64 + mh + mm * 16) * R_AP + kk * 8], R_AP);
                #pragma unroll
                for (int nn = 0; nn < 2; nn++)
                    wmma::load_matrix_sync(bf[nn],
                        &Ws[(nn * 16) * RW_PITCH + ks * 128 + ss * 16 + kk * 8], RW_PITCH);
                #pragma unroll
                for (int mm = 0; mm < 2; mm++)
                    #pragma unroll
                    for (int nn = 0; nn < 2; nn++)
                        wmma::mma_sync(acc[mm][nn], af[mm], bf[nn], acc[mm][nn]);
            }
            if (ss < 6) stage(buf, ss + 2);         // own subtile: no cross-warp hazard
        }

        __syncthreads();                            // all warps done reading As (WAR)

        // K-split partials -> Ps[ks][nn][64][20]
        #pragma unroll
        for (int mm = 0; mm < 2; mm++)
            #pragma unroll
            for (int nn = 0; nn < 2; nn++)
                wmma::store_matrix_sync(&Ps[((ks * 2 + nn) * 64 + mh + mm * 16) * R_AP],
                                        acc[mm][nn], R_AP, wmma::mem_row_major);
        __syncthreads();                            // cross-warp: partials ready

        // fused pointwise: sum 8 partials + xp + bias, LSTM cell update
        {
            float4 s = make_float4(0.f, 0.f, 0.f, 0.f);
            #pragma unroll
            for (int r = 0; r < 8; r++) {
                float4 p = *(const float4*)&Ps[((r * 2 + pnn) * 64 + pb) * R_AP + pcc];
                s.x += p.x; s.y += p.y; s.z += p.z; s.w += p.w;
            }
            float gi = s.x + xv.x + bv.x;
            float gf = s.y + xv.y + bv.y;
            float gg = s.z + xv.z + bv.z;
            float go = s.w + xv.w + bv.w;
            float si = 1.0f / (1.0f + __expf(-gi));
            float sf = 1.0f / (1.0f + __expf(-gf));
            float so = 1.0f / (1.0f + __expf(-go));
            cst = sf * cst + si * tanh_fast(gg);
            float h = so * tanh_fast(cst);
            hnext[(size_t)pb * HID + 8 * bk + pj] = h;
            if (mode == 0)
                g_hseq[((size_t)(t * 64 + pb)) * HID + 8 * bk + pj] = h;
            else if (t == ttb)
                g_lasth[(size_t)pb * HID + 8 * bk + pj] = h;
        }
        grid_barrier();                             // h(t+1) visible; Ps safe to reuse
    }
}

// ---------------- output projection ----------------
__global__ void out_kernel(const float* __restrict__ Wout, const float* __restrict__ bout,
                           float* __restrict__ out) {
    __shared__ float red[4];
    int b = blockIdx.x, tag = blockIdx.y;
    float s = 0.0f;
    for (int k = threadIdx.x; k < HID; k += 128)
        s += g_lasth[b * HID + k] * Wout[tag * HID + k];
    #pragma unroll
    for (int o = 16; o > 0; o >>= 1) s += __shfl_down_sync(0xffffffffu, s, o);
    if ((threadIdx.x & 31) == 0) red[threadIdx.x >> 5] = s;
    __syncthreads();
    if (threadIdx.x == 0)
        out[b * NTAG + tag] = red[0] + red[1] + red[2] + red[3] + bout[tag];
}

// ---------------- launch ----------------
extern "C" void kernel_launch(void* const* d_in, const int* in_sizes, int n_in,
                              void* d_out, int out_size) {
    const int*   x    = (const int*)d_in[0];
    const float* emb  = (const float*)d_in[1];
    const float* Wih0 = (const float*)d_in[2];
    const float* Whh0 = (const float*)d_in[3];
    const float* b0   = (const float*)d_in[4];
    const float* Wih1 = (const float*)d_in[5];
    const float* Whh1 = (const float*)d_in[6];
    const float* b1   = (const float*)d_in[7];
    const float* Wout = (const float*)d_in[8];
    const float* bout = (const float*)d_in[9];
    float* out = (float*)d_out;

    cudaFuncSetAttribute(recur_kernel, cudaFuncAttributeMaxDynamicSharedMemorySize,
                         R_SMEM_BYTES);
    cudaFuncSetAttribute(xproj_kernel, cudaFuncAttributeMaxDynamicSharedMemorySize,
                         X_SMEM_BYTES);

    float *p_seq0, *p_hseq, *p_xp, *pWih0, *pWih1, *pWhh0, *pWhh1, *pb0, *pb1;
    cudaGetSymbolAddress((void**)&p_seq0, g_seq0);
    cudaGetSymbolAddress((void**)&p_hseq, g_hseq);
    cudaGetSymbolAddress((void**)&p_xp,   g_xp);
    cudaGetSymbolAddress((void**)&pWih0,  g_Wih0p);
    cudaGetSymbolAddress((void**)&pWih1,  g_Wih1p);
    cudaGetSymbolAddress((void**)&pWhh0,  g_Whh0p);
    cudaGetSymbolAddress((void**)&pWhh1,  g_Whh1p);
    cudaGetSymbolAddress((void**)&pb0,    g_b0p);
    cudaGetSymbolAddress((void**)&pb1,    g_b1p);

    permute_kernel<<<G4, 256>>>(Wih0, Whh0, b0, Wih1, Whh1, b1);
    embed_kernel<<<ROWS, 128>>>(x, emb);
    lens_kernel<<<BATCH, 256>>>(x);

    dim3 xg(G4 / 128, ROWS / 128);                  // (32, 256)

    // Layer 0
    xproj_kernel<<<xg, 256, X_SMEM_BYTES>>>(p_seq0, pWih0, p_xp, EMBD);
    recur_kernel<<<RBLK, 512, R_SMEM_BYTES>>>(pWhh0, pb0, p_xp, 0);

    // Layer 1
    xproj_kernel<<<xg, 256, X_SMEM_BYTES>>>(p_hseq, pWih1, p_xp, HID);
    recur_kernel<<<RBLK, 512, R_SMEM_BYTES>>>(pWhh1, pb1, p_xp, 1);

    // Output head
    out_kernel<<<dim3(BATCH, NTAG), 128>>>(Wout, bout, out);
}

// round 12
// speedup vs baseline: 2.4034x; 2.4034x over previous
#include <cuda_runtime.h>
#include <cuda_bf16.h>
#include <cuda_fp16.h>
#include <mma.h>
#include <cstdint>
#include <cstddef>

using namespace nvcuda;

#define BATCH 64
#define TLEN  512
#define EMBD  512
#define HID   1024
#define G4    4096
#define NTAG  10
#define ROWS  (BATCH*TLEN)          // 32768
#define RBLK  128                   // persistent blocks in recurrent kernel

// ---------------- cp.async helpers ----------------
__device__ __forceinline__ void cp16(void* dst, const void* src) {
    unsigned d = (unsigned)__cvta_generic_to_shared(dst);
    asm volatile("cp.async.cg.shared.global [%0], [%1], 16;\n" :: "r"(d), "l"(src));
}
__device__ __forceinline__ void cp_commit() { asm volatile("cp.async.commit_group;\n"); }
template<int N> __device__ __forceinline__ void cp_wait() {
    asm volatile("cp.async.wait_group %0;\n" :: "n"(N));
}
__device__ __forceinline__ float tanh_fast(float x) {
    float y; asm("tanh.approx.f32 %0, %1;" : "=f"(y) : "f"(x)); return y;
}

// ---------------- recur smem layout (halves unless noted) ----------------
#define RW_PITCH 1048                          // W slice pitch (halves): 524w % 32 = 12
#define R_AP 40                                // h-panel pitch (halves): 20w % 32 = 20
#define R_AS_HALVES (2*4*64*R_AP)              // 20480 halves = 40960 B
#define R_PP 36                                // partial pitch (floats)
#define R_PS_FLOATS (4*64*R_PP)                // 9216 floats = 36864 B
#define R_SMEM_BYTES (32*RW_PITCH*2 + R_AS_HALVES*2 + R_PS_FLOATS*4)   // 144,896 B

// ---------------- xproj smem layout ----------------
#define X_AP 72                                // halves: 64 cols + 8 pad (36w % 32 = 4)
#define X_SMEM_BYTES (2*128*X_AP*2*2)          // As[2][128][72] + Bs[2][128][72] = 73,728 B

// ---------------- device scratch (static: no allocations allowed) ----------------
__device__ __half g_seq0[(size_t)ROWS*EMBD];    // embeddings (half), t-major rows (t*64+b)
__device__ float  g_xp  [(size_t)ROWS*G4];      // x_proj scratch fp32 (reused by both layers)
__device__ __half g_hseq[(size_t)ROWS*HID];     // layer-0 hidden sequence (half)
__device__ __half g_h[2][BATCH*HID];            // double-buffered recurrent h (half)
__device__ float  g_lasth[BATCH*HID];           // layer-1 h at t = lens-1 (fp32)
__device__ __half g_Wih0h[(size_t)G4*EMBD];     // gate-permuted fp16 weights
__device__ __half g_Whh0h[(size_t)G4*HID];
__device__ __half g_Wih1h[(size_t)G4*HID];
__device__ __half g_Whh1h[(size_t)G4*HID];
__device__ float  g_b0p[G4];
__device__ float  g_b1p[G4];
__device__ int    g_tt[BATCH];                  // target timestep per batch (lens-1)
__device__ unsigned g_barcnt = 0;               // monotonic grid-barrier ticket counter

// ---------------- grid barrier: monotonic ticket scheme (R7-proven) ----------------
__device__ __forceinline__ void grid_barrier() {
    __syncthreads();
    if (threadIdx.x == 0) {
        __threadfence();                               // release our block's writes
        unsigned t = atomicAdd(&g_barcnt, 1u);
        unsigned target = ((t >> 7) + 1u) << 7;
        while ((int)(*(volatile unsigned*)&g_barcnt - target) < 0) {}
        __threadfence();                               // acquire
    }
    __syncthreads();
}

// ---------------- preprocessing ----------------
// Permute gate rows: out row 4*j+g  <-  in row g*HID+j, convert to fp16.
__global__ void permute_kernel(const float* __restrict__ Wih0, const float* __restrict__ Whh0,
                               const float* __restrict__ b0,
                               const float* __restrict__ Wih1, const float* __restrict__ Whh1,
                               const float* __restrict__ b1) {
    int p = blockIdx.x;                 // 0..4095
    int j = p >> 2, q = p & 3;
    size_t src = (size_t)(q * HID + j);
    for (int d = threadIdx.x; d < EMBD; d += blockDim.x)
        g_Wih0h[(size_t)p*EMBD + d] = __float2half_rn(Wih0[src*EMBD + d]);
    for (int d = threadIdx.x; d < HID; d += blockDim.x) {
        g_Whh0h[(size_t)p*HID + d] = __float2half_rn(Whh0[src*HID + d]);
        g_Wih1h[(size_t)p*HID + d] = __float2half_rn(Wih1[src*HID + d]);
        g_Whh1h[(size_t)p*HID + d] = __float2half_rn(Whh1[src*HID + d]);
    }
    if (threadIdx.x == 0) { g_b0p[p] = b0[src]; g_b1p[p] = b1[src]; }
}

// Embedding gather into t-major half layout: row r = t*64 + b
__global__ void embed_kernel(const int* __restrict__ x, const float* __restrict__ emb) {
    int r = blockIdx.x;
    int b = r & 63, t = r >> 6;
    int tok = x[b * TLEN + t];
    const float4* src = (const float4*)&emb[(size_t)tok * EMBD];
    __half2* dst = (__half2*)&g_seq0[(size_t)r * EMBD];
    float4 v = src[threadIdx.x];                 // 128 threads = 128 float4 = 512 floats
    dst[2 * threadIdx.x]     = __floats2half2_rn(v.x, v.y);
    dst[2 * threadIdx.x + 1] = __floats2half2_rn(v.z, v.w);
}

// lens + target timestep
__global__ void lens_kernel(const int* __restrict__ x) {
    __shared__ int red[8];
    int b = blockIdx.x;
    int c = 0;
    for (int t = threadIdx.x; t < TLEN; t += 256) c += (x[b * TLEN + t] == 0);
    #pragma unroll
    for (int o = 16; o > 0; o >>= 1) c += __shfl_down_sync(0xffffffffu, c, o);
    if ((threadIdx.x & 31) == 0) red[threadIdx.x >> 5] = c;
    __syncthreads();
    if (threadIdx.x == 0) {
        int tot = 0;
        #pragma unroll
        for (int w = 0; w < 8; w++) tot += red[w];
        int tt = TLEN - tot - 1;          // lens-1
        if (tt < 0) tt += TLEN;           // wrap like Python negative index
        g_tt[b] = tt;
    }
}

// ---------------- x_proj GEMM (fp16, pipelined): out[r][p] = sum_k A[r][k]*W[p][k]
// Block tile 128x128, 8 warps of 32x64, BK=64, 2-stage cp.async pipeline.
__global__ void __launch_bounds__(256, 2) xproj_kernel(const __half* __restrict__ A,
                                                       const __half* __restrict__ W,
                                                       float* __restrict__ out, int K) {
    extern __shared__ __half xsm[];
    __half* As = xsm;                       // [2][128][72]
    __half* Bs = xsm + 2 * 128 * X_AP;      // [2][128][72]
    const int tid = threadIdx.x;
    const int warp = tid >> 5;
    const int m0 = blockIdx.y * 128, n0 = blockIdx.x * 128;
    const int wm = (warp & 3) * 32, wn = (warp >> 2) * 64;

    wmma::fragment<wmma::accumulator, 16, 16, 16, float> acc[2][4];
    #pragma unroll
    for (int i = 0; i < 2; i++)
        #pragma unroll
        for (int j = 0; j < 4; j++) wmma::fill_fragment(acc[i][j], 0.0f);

    const int sr = tid >> 3;                // 0..31
    const int sc = (tid & 7) << 3;          // 0..56 (halves)

    auto stage = [&](int buf, int k0) {
        #pragma unroll
        for (int p = 0; p < 4; p++) {
            int r = sr + p * 32;
            cp16(&As[(buf * 128 + r) * X_AP + sc], &A[(size_t)(m0 + r) * K + k0 + sc]);
        }
        #pragma unroll
        for (int p = 0; p < 4; p++) {
            int r = sr + p * 32;
            cp16(&Bs[(buf * 128 + r) * X_AP + sc], &W[(size_t)(n0 + r) * K + k0 + sc]);
        }
        cp_commit();
    };

    stage(0, 0);
    stage(1, 64);
    const int NC = K >> 6;
    for (int ch = 0; ch < NC; ch++) {
        if (ch < NC - 1) cp_wait<1>(); else cp_wait<0>();
        __syncthreads();
        int buf = ch & 1;
        #pragma unroll
        for (int kk = 0; kk < 4; kk++) {
            wmma::fragment<wmma::matrix_a, 16, 16, 16, __half, wmma::row_major> af[2];
            wmma::fragment<wmma::matrix_b, 16, 16, 16, __half, wmma::col_major> bf[4];
            #pragma unroll
            for (int i = 0; i < 2; i++)
                wmma::load_matrix_sync(af[i], &As[(buf * 128 + wm + 16 * i) * X_AP + kk * 16], X_AP);
            #pragma unroll
            for (int j = 0; j < 4; j++)
                wmma::load_matrix_sync(bf[j], &Bs[(buf * 128 + wn + 16 * j) * X_AP + kk * 16], X_AP);
            #pragma unroll
            for (int i = 0; i < 2; i++)
                #pragma unroll
                for (int j = 0; j < 4; j++)
                    wmma::mma_sync(acc[i][j], af[i], bf[j], acc[i][j]);
        }
        __syncthreads();
        if (ch + 2 < NC) stage(buf, (ch + 2) * 64);
    }
    #pragma unroll
    for (int i = 0; i < 2; i++)
        #pragma unroll
        for (int j = 0; j < 4; j++)
            wmma::store_matrix_sync(&out[(size_t)(m0 + wm + 16 * i) * G4 + n0 + wn + 16 * j],
                                    acc[i][j], G4, wmma::mem_row_major);
}

// ---------------- persistent recurrent kernel (fp16 operands, fp32 accum) -------
// R7 skeleton: 128 blocks x 256 threads; block bk owns permuted gate rows
// [32*bk, 32*bk+32) = hidden units [8*bk, 8*bk+8). 8 warps = 4 K-splits x 2
// M-halves, warp tile 32x32. Warp-private staging (rows [mh,mh+32) x 32 halves
// per superstep) keeps the inner loop barrier-free: per-warp cp.async.wait +
// __syncwarp only. Partials in their OWN fp32 region (no aliasing). One block
// sync before the cross-warp reduction, one grid barrier per step.
__global__ void __launch_bounds__(256) recur_kernel(const __half* __restrict__ Whh,
                                                    const float* __restrict__ bias,
                                                    const float* __restrict__ xp,
                                                    int mode) {
    extern __shared__ __half smh[];
    __half* Ws = smh;                               // [32][1048]
    __half* As = Ws + 32 * RW_PITCH;                // [2][4][64][40]
    float*  Ps = (float*)(As + R_AS_HALVES);        // [4][64][36] fp32

    const int tid = threadIdx.x;
    const int warp = tid >> 5;
    const int lane = tid & 31;
    const int bk = blockIdx.x;
    const int ks = warp >> 1;                       // K-split 0..3 (256 cols each)
    const int mh = (warp & 1) * 32;                 // M half (batch rows)

    // ---- stage W slice rows [32*bk, 32*bk+32), full K=1024 halves ----
    for (int i = tid; i < 32 * 128; i += 256) {     // 128 float4 (16B) per gate row
        int r = i >> 7, c = i & 127;
        float4 v = *(const float4*)((const char*)&Whh[((size_t)(32 * bk + r)) * HID] + c * 16);
        *(float4*)((char*)&Ws[r * RW_PITCH] + c * 16) = v;
    }
    // per-thread persistent state (pointwise mapping is static across steps)
    const int pb0 = tid >> 3, pj0 = tid & 7;
    const float4 bv = *(const float4*)&bias[32 * bk + pj0 * 4];
    const int tt0 = g_tt[pb0];
    const int tt1 = g_tt[pb0 + 32];
    float c0 = 0.0f, c1 = 0.0f;                     // cell states
    {   // zero this block's slice of g_h[0]
        int b = tid >> 2, j2 = (tid & 3) * 2;
        g_h[0][b * HID + 8 * bk + j2]     = __float2half(0.0f);
        g_h[0][b * HID + 8 * bk + j2 + 1] = __float2half(0.0f);
    }
    grid_barrier();                                 // W staged + h0 zeroed everywhere

    // warp-private staging geometry: 32 rows x 32 halves per superstep
    const int srow = lane >> 2;                     // 0..7  (+8 per i)
    const int scol = (lane & 3) << 3;               // 0,8,16,24 (halves)

    for (int t = 0; t < TLEN; t++) {
        const __half* hprev = g_h[t & 1];
        __half* hnext = g_h[(t + 1) & 1];

        // prefetch xp (independent of the recurrence)
        float4 xv0 = __ldg((const float4*)&xp[((size_t)(t * 64 + pb0)) * G4 + 32 * bk + pj0 * 4]);
        float4 xv1 = __ldg((const float4*)&xp[((size_t)(t * 64 + pb0 + 32)) * G4 + 32 * bk + pj0 * 4]);

        wmma::fragment<wmma::accumulator, 16, 16, 16, float> acc[2][2];
        #pragma unroll
        for (int i = 0; i < 2; i++)
            #pragma unroll
            for (int j = 0; j < 2; j++) wmma::fill_fragment(acc[i][j], 0.0f);

        // warp-private stage: rows [mh, mh+32) x cols [ks*256+ss*32, +32)
        auto stage = [&](int buf, int ss) {
            #pragma unroll
            for (int i = 0; i < 4; i++) {
                int row = mh + i * 8 + srow;
                cp16(&As[((buf * 4 + ks) * 64 + row) * R_AP + scol],
                     &hprev[(size_t)row * HID + ks * 256 + ss * 32 + scol]);
            }
            cp_commit();
        };

        stage(0, 0);
        stage(1, 1);
        #pragma unroll
        for (int ss = 0; ss < 8; ss++) {
            if (ss < 7) cp_wait<1>(); else cp_wait<0>();
            __syncwarp();                           // staged data visible warp-wide
            int buf = ss & 1;
            #pragma unroll
            for (int kk = 0; kk < 2; kk++) {
                wmma::fragment<wmma::matrix_a, 16, 16, 16, __half, wmma::row_major> af[2];
                wmma::fragment<wmma::matrix_b, 16, 16, 16, __half, wmma::col_major> bf[2];
                #pragma unroll
                for (int mm = 0; mm < 2; mm++)
                    wmma::load_matrix_sync(af[mm],
                        &As[((buf * 4 + ks) * 64 + mh + mm * 16) * R_AP + kk * 16], R_AP);
                #pragma unroll
                for (int nn = 0; nn < 2; nn++)
                    wmma::load_matrix_sync(bf[nn],
                        &Ws[(nn * 16) * RW_PITCH + ks * 256 + ss * 32 + kk * 16], RW_PITCH);
                #pragma unroll
                for (int mm = 0; mm < 2; mm++)
                    #pragma unroll
                    for (int nn = 0; nn < 2; nn++)
                        wmma::mma_sync(acc[mm][nn], af[mm], bf[nn], acc[mm][nn]);
            }
            if (ss < 6) stage(buf, ss + 2);         // own subtile: no cross-warp hazard
        }

        // K-split partials -> Ps (separate fp32 region, no aliasing)
        #pragma unroll
        for (int mm = 0; mm < 2; mm++)
            #pragma unroll
            for (int nn = 0; nn < 2; nn++)
                wmma::store_matrix_sync(&Ps[(ks * 64 + mh + mm * 16) * R_PP + nn * 16],
                                        acc[mm][nn], R_PP, wmma::mem_row_major);
        __syncthreads();                            // cross-warp: partials ready

        // fused pointwise: sum 4 partials + xp + bias, LSTM cell update
        #pragma unroll
        for (int it = 0; it < 2; it++) {
            int b = pb0 + it * 32;
            int jj = pj0;
            float4 xv = it ? xv1 : xv0;
            int col = jj * 4;
            float4 p0 = *(const float4*)&Ps[(0 * 64 + b) * R_PP + col];
            float4 p1 = *(const float4*)&Ps[(1 * 64 + b) * R_PP + col];
            float4 p2 = *(const float4*)&Ps[(2 * 64 + b) * R_PP + col];
            float4 p3 = *(const float4*)&Ps[(3 * 64 + b) * R_PP + col];
            float gi = p0.x + p1.x + p2.x + p3.x + xv.x + bv.x;
            float gf = p0.y + p1.y + p2.y + p3.y + xv.y + bv.y;
            float gg = p0.z + p1.z + p2.z + p3.z + xv.z + bv.z;
            float go = p0.w + p1.w + p2.w + p3.w + xv.w + bv.w;
            float c = it ? c1 : c0;
            float si = 1.0f / (1.0f + __expf(-gi));
            float sf = 1.0f / (1.0f + __expf(-gf));
            float so = 1.0f / (1.0f + __expf(-go));
            c = sf * c + si * tanh_fast(gg);
            if (it) c1 = c; else c0 = c;
            float h = so * tanh_fast(c);
            hnext[(size_t)b * HID + 8 * bk + jj] = __float2half(h);
            if (mode == 0)
                g_hseq[((size_t)(t * 64 + b)) * HID + 8 * bk + jj] = __float2half(h);
            else if (t == (it ? tt1 : tt0))
                g_lasth[(size_t)b * HID + 8 * bk + jj] = h;
        }
        grid_barrier();                             // h(t+1) visible; Ps safe to reuse
    }
}

// ---------------- output projection ----------------
__global__ void out_kernel(const float* __restrict__ Wout, const float* __restrict__ bout,
                           float* __restrict__ out) {
    __shared__ float red[4];
    int b = blockIdx.x, tag = blockIdx.y;
    float s = 0.0f;
    for (int k = threadIdx.x; k < HID; k += 128)
        s += g_lasth[b * HID + k] * Wout[tag * HID + k];
    #pragma unroll
    for (int o = 16; o > 0; o >>= 1) s += __shfl_down_sync(0xffffffffu, s, o);
    if ((threadIdx.x & 31) == 0) red[threadIdx.x >> 5] = s;
    __syncthreads();
    if (threadIdx.x == 0)
        out[b * NTAG + tag] = red[0] + red[1] + red[2] + red[3] + bout[tag];
}

// ---------------- launch ----------------
extern "C" void kernel_launch(void* const* d_in, const int* in_sizes, int n_in,
                              void* d_out, int out_size) {
    const int*   x    = (const int*)d_in[0];
    const float* emb  = (const float*)d_in[1];
    const float* Wih0 = (const float*)d_in[2];
    const float* Whh0 = (const float*)d_in[3];
    const float* b0   = (const float*)d_in[4];
    const float* Wih1 = (const float*)d_in[5];
    const float* Whh1 = (const float*)d_in[6];
    const float* b1   = (const float*)d_in[7];
    const float* Wout = (const float*)d_in[8];
    const float* bout = (const float*)d_in[9];
    float* out = (float*)d_out;

    cudaFuncSetAttribute(recur_kernel, cudaFuncAttributeMaxDynamicSharedMemorySize,
                         R_SMEM_BYTES);
    cudaFuncSetAttribute(xproj_kernel, cudaFuncAttributeMaxDynamicSharedMemorySize,
                         X_SMEM_BYTES);

    __half *p_seq0, *p_hseq, *pWih0, *pWih1, *pWhh0, *pWhh1;
    float *p_xp, *pb0, *pb1;
    cudaGetSymbolAddress((void**)&p_seq0, g_seq0);
    cudaGetSymbolAddress((void**)&p_hseq, g_hseq);
    cudaGetSymbolAddress((void**)&p_xp,   g_xp);
    cudaGetSymbolAddress((void**)&pWih0,  g_Wih0h);
    cudaGetSymbolAddress((void**)&pWih1,  g_Wih1h);
    cudaGetSymbolAddress((void**)&pWhh0,  g_Whh0h);
    cudaGetSymbolAddress((void**)&pWhh1,  g_Whh1h);
    cudaGetSymbolAddress((void**)&pb0,    g_b0p);
    cudaGetSymbolAddress((void**)&pb1,    g_b1p);

    permute_kernel<<<G4, 256>>>(Wih0, Whh0, b0, Wih1, Whh1, b1);
    embed_kernel<<<ROWS, 128>>>(x, emb);
    lens_kernel<<<BATCH, 256>>>(x);

    dim3 xg(G4 / 128, ROWS / 128);                  // (32, 256)

    // Layer 0
    xproj_kernel<<<xg, 256, X_SMEM_BYTES>>>(p_seq0, pWih0, p_xp, EMBD);
    recur_kernel<<<RBLK, 256, R_SMEM_BYTES>>>(pWhh0, pb0, p_xp, 0);

    // Layer 1
    xproj_kernel<<<xg, 256, X_SMEM_BYTES>>>(p_hseq, pWih1, p_xp, HID);
    recur_kernel<<<RBLK, 256, R_SMEM_BYTES>>>(pWhh1, pb1, p_xp, 1);

    // Output head
    out_kernel<<<dim3(BATCH, NTAG), 128>>>(Wout, bout, out);
}